// round 11
// baseline (speedup 1.0000x reference)
#include <cuda_runtime.h>
#include <cstdint>

// Problem constants
#define Nn 32
#define Cc 64
#define HW 16384            // 128*128
#define CHW (Cc*HW)         // 1048576
#define NCOLS_S 58255
#define NCHUNK 911
#define EPSF 0.01f
#define GRID_GRAM 148
#define GRID_APPLY 4096     // 524288 cols / 128 per block

typedef unsigned long long ull;
typedef unsigned int u32;

// bf16x2 pack: high 16 bits = bf16(a_hi), low 16 = bf16(b_lo)
__device__ __forceinline__ u32 bf2(float a_hi, float b_lo) {
    u32 r; asm("cvt.rn.bf16x2.f32 %0, %1, %2;" : "=r"(r) : "f"(a_hi), "f"(b_lo));
    return r;
}
__device__ __forceinline__ void ubf2(u32 v, float& lo, float& hi) {
    lo = __uint_as_float(v << 16);
    hi = __uint_as_float(v & 0xFFFF0000u);
}
__device__ __forceinline__ u32 smem_u32(const void* p) {
    u32 a;
    asm("{ .reg .u64 t; cvta.to.shared.u64 t, %1; cvt.u32.u64 %0, t; }" : "=r"(a) : "l"(p));
    return a;
}

// ---------------- mma.sync helpers ----------------
__device__ __forceinline__ void ldm_x4(u32& r0, u32& r1, u32& r2, u32& r3, u32 addr) {
    asm volatile("ldmatrix.sync.aligned.m8n8.x4.shared.b16 {%0,%1,%2,%3}, [%4];"
                 : "=r"(r0), "=r"(r1), "=r"(r2), "=r"(r3) : "r"(addr));
}
__device__ __forceinline__ void ldm_x2t(u32& r0, u32& r1, u32 addr) {
    asm volatile("ldmatrix.sync.aligned.m8n8.x2.trans.shared.b16 {%0,%1}, [%2];"
                 : "=r"(r0), "=r"(r1) : "r"(addr));
}
__device__ __forceinline__ void mma_bf16(float* d, const u32* a, const u32* b) {
    asm volatile(
        "mma.sync.aligned.m16n8k16.row.col.f32.bf16.bf16.f32 "
        "{%0,%1,%2,%3}, {%4,%5,%6,%7}, {%8,%9}, {%0,%1,%2,%3};"
        : "+f"(d[0]), "+f"(d[1]), "+f"(d[2]), "+f"(d[3])
        : "r"(a[0]), "r"(a[1]), "r"(a[2]), "r"(a[3]), "r"(b[0]), "r"(b[1]));
}

// ---------------- device scratch ----------------
__device__ float g_part[GRID_GRAM * 4096];
__device__ float g_rspart[GRID_GRAM * 64];
__device__ float g_gram[4096];
__device__ float g_rowsum[64];
__device__ __align__(16) u32 g_wpack[4096];   // [0:2048) Wh, [2048:4096) Wl
__device__ float g_dmean[64];

// =====================================================================
// Pass 1: Gram of subsampled columns + row sums (measured-best shape)
// =====================================================================
__global__ void __launch_bounds__(256) gram_kernel(const float* __restrict__ x) {
    __shared__ float asub[64][64];
    __shared__ float ps[256];

    const int t = threadIdx.x;
    const int bid = blockIdx.x;
    const int b = t & 63;
    const int g = t >> 6;
    const int i0 = (t >> 4) * 4, j0 = (t & 15) * 4;

    float acc[4][4];
#pragma unroll
    for (int p = 0; p < 4; p++)
#pragma unroll
        for (int q = 0; q < 4; q++) acc[p][q] = 0.f;
    float rs = 0.f;

    for (int chunk = bid; chunk < NCHUNK; chunk += GRID_GRAM) {
        float vals[16];
#pragma unroll
        for (int k = 0; k < 16; k++) {
            const int scol = g * 16 + k;
            const int s = chunk * 64 + scol;
            float v = 0.f;
            if (s < NCOLS_S) {
                const int col = s * 9;
                const int n = col >> 14;
                const int p = col & 16383;
                v = x[n * CHW + b * HW + p];
            }
            vals[k] = v;
            rs += v;
        }
        __syncthreads();
#pragma unroll
        for (int k = 0; k < 16; k++) asub[g * 16 + k][b] = vals[k];
        __syncthreads();

#pragma unroll 4
        for (int scol = 0; scol < 64; scol++) {
            const float4 av = *(const float4*)&asub[scol][i0];
            const float4 bv = *(const float4*)&asub[scol][j0];
            const float ar[4] = {av.x, av.y, av.z, av.w};
            const float br[4] = {bv.x, bv.y, bv.z, bv.w};
#pragma unroll
            for (int p = 0; p < 4; p++)
#pragma unroll
                for (int q = 0; q < 4; q++)
                    acc[p][q] = fmaf(ar[p], br[q], acc[p][q]);
        }
    }

    float* gp = &g_part[bid * 4096];
#pragma unroll
    for (int p = 0; p < 4; p++)
#pragma unroll
        for (int q = 0; q < 4; q++)
            gp[(i0 + p) * 64 + (j0 + q)] = acc[p][q];

    __syncthreads();
    ps[t] = rs;
    __syncthreads();
    if (t < 64)
        g_rspart[bid * 64 + t] = ps[t] + ps[t + 64] + ps[t + 128] + ps[t + 192];
}

// =====================================================================
// Deterministic reduction (measured-best shape)
// =====================================================================
__global__ void __launch_bounds__(256) reduce_kernel() {
    const int idx = blockIdx.x * 256 + threadIdx.x;
    float s = 0.f;
    for (int k = 0; k < GRID_GRAM; k++) s += g_part[k * 4096 + idx];
    g_gram[idx] = s;
    if (blockIdx.x == 0 && threadIdx.x < 64) {
        float r = 0.f;
        for (int k = 0; k < GRID_GRAM; k++) r += g_rspart[k * 64 + threadIdx.x];
        g_rowsum[threadIdx.x] = r;
    }
}

// =====================================================================
// Newton-Schulz via mma.sync — dual-phase schedule, 512 thr (16 warps).
// Matrices as bf16 hi/lo images: [64 rows][72 bf16] (144B rows), 5 slots.
// Each sub-matmul uses 8 warps, warp = 16 rows x 32 cols (R7-best shape).
// Phase T: warps 0-7.  Dual phase: warps 0-7 -> U1=Y@T, warps 8-15 -> U2=T@Z.
// =====================================================================
#define SLOT_BYTES 18432           // hi(9216) + lo(9216)
#define NS_SMEM (5 * SLOT_BYTES + 2048)

__device__ __forceinline__ void ns_mm64(char* smc, u32 sbase,
                                        int dst, int As, int Bs,
                                        int role, int lane, bool thalf) {
    const int mt = role & 3;
    const int nh = role >> 2;

    float d[4][4];
#pragma unroll
    for (int nt = 0; nt < 4; nt++)
#pragma unroll
        for (int r = 0; r < 4; r++) d[nt][r] = 0.f;

    const u32 Ahi = sbase + (u32)As * SLOT_BYTES;
    const u32 Alo = Ahi + 9216;
    const u32 Bhi = sbase + (u32)Bs * SLOT_BYTES;
    const u32 Blo = Bhi + 9216;

    const u32 a_base = (u32)(mt * 16 + (lane & 15)) * 144 + (u32)(lane >> 4) * 16;
    const u32 b_base = (u32)(lane & 15) * 144 + (u32)nh * 64;

#pragma unroll
    for (int ks = 0; ks < 4; ks++) {
        u32 ah[4], al[4];
        ldm_x4(ah[0], ah[1], ah[2], ah[3], Ahi + a_base + (u32)ks * 32);
        ldm_x4(al[0], al[1], al[2], al[3], Alo + a_base + (u32)ks * 32);
        const u32 brow = b_base + (u32)(ks * 16) * 144;
#pragma unroll
        for (int nt = 0; nt < 4; nt++) {
            u32 bh[2], bl[2];
            ldm_x2t(bh[0], bh[1], Bhi + brow + (u32)nt * 16);
            ldm_x2t(bl[0], bl[1], Blo + brow + (u32)nt * 16);
            mma_bf16(d[nt], ah, bh);
            mma_bf16(d[nt], ah, bl);
            mma_bf16(d[nt], al, bh);
        }
    }

    u32* Dhi = (u32*)(smc + dst * SLOT_BYTES);
    u32* Dlo = (u32*)(smc + dst * SLOT_BYTES + 9216);
    const int r0 = mt * 16 + (lane >> 2);
#pragma unroll
    for (int nt = 0; nt < 4; nt++) {
        const int c0 = nh * 32 + nt * 8 + (lane & 3) * 2;
        float v0 = d[nt][0], v1 = d[nt][1], v2 = d[nt][2], v3 = d[nt][3];
        if (thalf) {
            v0 = (r0 == c0     ? 1.5f : 0.f) - 0.5f * v0;
            v1 = (r0 == c0 + 1 ? 1.5f : 0.f) - 0.5f * v1;
            v2 = (r0 + 8 == c0     ? 1.5f : 0.f) - 0.5f * v2;
            v3 = (r0 + 8 == c0 + 1 ? 1.5f : 0.f) - 0.5f * v3;
        }
        {
            const u32 h = bf2(v1, v0);
            float e0, e1; ubf2(h, e0, e1);
            Dhi[r0 * 36 + (c0 >> 1)] = h;
            Dlo[r0 * 36 + (c0 >> 1)] = bf2(v1 - e1, v0 - e0);
        }
        {
            const u32 h = bf2(v3, v2);
            float e2, e3; ubf2(h, e2, e3);
            Dhi[(r0 + 8) * 36 + (c0 >> 1)] = h;
            Dlo[(r0 + 8) * 36 + (c0 >> 1)] = bf2(v3 - e3, v2 - e2);
        }
    }
}

__global__ void __launch_bounds__(512) ns_kernel() {
    extern __shared__ char smc[];
    const u32 sbase = smem_u32(smc);
    float* red = (float*)(smc + 5 * SLOT_BYTES);

    const int t = threadIdx.x;
    const int wid = t >> 5;
    const int lane = t & 31;
    const float invn = 1.0f / (float)NCOLS_S;

    // ---- prologue (threads 0-255): cov, Frobenius norm ----
    const int prow = (t >> 2) & 63;
    const int pcol0 = (t & 3) * 16;
    float v[16];
    float ss = 0.f;
    if (t < 256) {
#pragma unroll
        for (int c = 0; c < 16; c++) {
            const int j = pcol0 + c;
            float val = g_gram[prow * 64 + j] * invn + ((prow == j) ? EPSF : 0.f);
            v[c] = val;
            ss += val * val;
        }
    }
    red[t] = (t < 256) ? ss : 0.f;
    __syncthreads();
    for (int off = 256; off > 0; off >>= 1) {
        if (t < off) red[t] += red[t + off];
        __syncthreads();
    }
    const float normA = sqrtf(red[0]);
    const float inv = 1.0f / normA;

    // ---- build Y (slot0), Z = I (slot1) ----
    if (t < 256) {
        u32* Yhi = (u32*)(smc);
        u32* Ylo = (u32*)(smc + 9216);
        u32* Zhi = (u32*)(smc + SLOT_BYTES);
        u32* Zlo = (u32*)(smc + SLOT_BYTES + 9216);
#pragma unroll
        for (int p = 0; p < 8; p++) {
            const float y0 = v[2 * p] * inv;
            const float y1 = v[2 * p + 1] * inv;
            const u32 h = bf2(y1, y0);
            float e0, e1; ubf2(h, e0, e1);
            const int ui = prow * 36 + (pcol0 >> 1) + p;
            Yhi[ui] = h;
            Ylo[ui] = bf2(y1 - e1, y0 - e0);
            const int c0 = pcol0 + 2 * p;
            u32 ih = 0;
            if (prow == c0) ih = 0x00003F80u;
            else if (prow == c0 + 1) ih = 0x3F800000u;
            Zhi[ui] = ih;
            Zlo[ui] = 0u;
        }
    }
    __syncthreads();

    // ---- 5 NS iterations, dual-phase ----
    int Y = 0, Z = 1, T = 2, U1 = 3, U2 = 4;
    for (int it = 0; it < 5; it++) {
        // Phase A: T = 1.5I - 0.5 * Z@Y  (warps 0-7)
        if (wid < 8)
            ns_mm64(smc, sbase, T, Z, Y, wid, lane, true);
        __syncthreads();
        if (it < 4) {
            // Phase B: U1 = Y@T (warps 0-7) || U2 = T@Z (warps 8-15)
            if (wid < 8)
                ns_mm64(smc, sbase, U1, Y, T, wid, lane, false);
            else
                ns_mm64(smc, sbase, U2, T, Z, wid - 8, lane, false);
            __syncthreads();
            const int oldY = Y, oldZ = Z;
            Y = U1; Z = U2; U1 = oldY; U2 = oldZ;
        } else {
            // Final: only Z' = T@Z needed (Y is dead)
            if (wid < 8)
                ns_mm64(smc, sbase, U1, T, Z, wid, lane, false);
            __syncthreads();
            Z = U1;
        }
    }

    const float sc = 1.0f / sqrtf(normA);
    const u32* Zhi = (const u32*)(smc + Z * SLOT_BYTES);
    const u32* Zlo = (const u32*)(smc + Z * SLOT_BYTES + 9216);

    // ---- emit W hi/lo (row-major [64][32] u32) ----
    if (t < 256) {
#pragma unroll
        for (int p = 0; p < 8; p++) {
            const int ui = prow * 36 + (pcol0 >> 1) + p;
            float h0, h1, l0, l1;
            ubf2(Zhi[ui], h0, h1);
            ubf2(Zlo[ui], l0, l1);
            const float d0 = (h0 + l0) * sc;
            const float d1 = (h1 + l1) * sc;
            const u32 h = bf2(d1, d0);
            float e0, e1; ubf2(h, e0, e1);
            const u32 gi = prow * 32 + (pcol0 >> 1) + p;
            g_wpack[gi] = h;
            g_wpack[2048 + gi] = bf2(d1 - e1, d0 - e0);
        }
    }
    __syncthreads();
    if (t < 64) {
        float dm = 0.f;
        for (int p = 0; p < 32; p++) {
            float h0, h1, l0, l1;
            ubf2(Zhi[t * 36 + p], h0, h1);
            ubf2(Zlo[t * 36 + p], l0, l1);
            dm += (h0 + l0) * sc * (g_rowsum[2 * p] * invn);
            dm += (h1 + l1) * sc * (g_rowsum[2 * p + 1] * invn);
        }
        g_dmean[t] = dm;
    }
}

// =====================================================================
// Pass 2 (mma.sync bf16 split-precision), 128-col tiles.
// Warp w: m-group = w>>2 (32 ch = 2 m-tiles), col-strip = (w&3)*32 (4 n-tiles).
// (measured-best shape)
// =====================================================================
#define XSTRIDE_H 136              // bf16 per X row (272B)
#define SM_XH 0
#define SM_XL 17408
#define SM_WH 34816
#define SM_WL 44032
#define SM_DM 53248
#define APPLY_SMEM (SM_DM + 256)

__global__ void __launch_bounds__(256, 3) apply_mma_kernel(const float* __restrict__ x,
                                                           float* __restrict__ y) {
    extern __shared__ char smc[];
    const u32 sbase = smem_u32(smc);
    const int t = threadIdx.x;
    const int wid = t >> 5;
    const int lane = t & 31;

    // ---- stage W (padded rows: 36 u32 = 72 bf16) + dmean ----
    {
        u32* wh = (u32*)(smc + SM_WH);
        u32* wl = (u32*)(smc + SM_WL);
#pragma unroll
        for (int k = 0; k < 8; k++) {
            const int u = k * 256 + t;
            const int i = u >> 5;
            const int jc = u & 31;
            wh[i * 36 + jc] = g_wpack[u];
            wl[i * 36 + jc] = g_wpack[2048 + u];
        }
        if (t < 64) ((float*)(smc + SM_DM))[t] = g_dmean[t];
    }

    // ---- stage X tile (64 rows x 128 cols): f32 -> bf16 hi/lo ----
    const int gcol0 = blockIdx.x * 128;
    const int n = gcol0 >> 14;
    const int p0 = gcol0 & 16383;
    const float* xb = x + (size_t)n * CHW + p0;

    {
        const int c = lane * 4;
        const int row0 = wid * 8;
        ull* xhp = (ull*)(smc + SM_XH);
        ull* xlp = (ull*)(smc + SM_XL);
#pragma unroll
        for (int r = 0; r < 8; r++) {
            const int row = row0 + r;
            const float4 vv = *(const float4*)&xb[(size_t)row * HW + c];
            const u32 h0 = bf2(vv.y, vv.x);
            const u32 h1 = bf2(vv.w, vv.z);
            float e0, e1, e2, e3;
            ubf2(h0, e0, e1);
            ubf2(h1, e2, e3);
            const u32 l0 = bf2(vv.y - e1, vv.x - e0);
            const u32 l1 = bf2(vv.w - e3, vv.z - e2);
            const int di = (row * XSTRIDE_H + c) >> 2;
            xhp[di] = ((ull)h1 << 32) | h0;
            xlp[di] = ((ull)l1 << 32) | l0;
        }
    }
    __syncthreads();

    // ---- MMA mainloop: warp = 2 m-tiles x 4 n-tiles ----
    const int cs = wid & 3;
    const int mg = wid >> 2;
    const int wc0 = cs * 32;

    float d[2][4][4];
#pragma unroll
    for (int m = 0; m < 2; m++)
#pragma unroll
        for (int ni = 0; ni < 4; ni++)
#pragma unroll
            for (int r = 0; r < 4; r++) d[m][ni][r] = 0.f;

    const u32 a_h_base = sbase + SM_WH + (u32)(mg * 32 + (lane & 15)) * 144 + (u32)(lane >> 4) * 16;
    const u32 a_l_base = a_h_base + (SM_WL - SM_WH);
    const u32 b_h_base = sbase + SM_XH + (u32)(lane & 15) * 272 + (u32)wc0 * 2;
    const u32 b_l_base = b_h_base + (SM_XL - SM_XH);

#pragma unroll
    for (int ks = 0; ks < 4; ks++) {
        u32 bh[4][2], bl[4][2];
        const u32 brow = (u32)(ks * 16) * 272;
#pragma unroll
        for (int ni = 0; ni < 4; ni++) {
            ldm_x2t(bh[ni][0], bh[ni][1], b_h_base + brow + (u32)ni * 16);
            ldm_x2t(bl[ni][0], bl[ni][1], b_l_base + brow + (u32)ni * 16);
        }
#pragma unroll
        for (int m = 0; m < 2; m++) {
            u32 ah[4], al[4];
            const u32 aoff = (u32)(m * 16) * 144 + (u32)ks * 32;
            ldm_x4(ah[0], ah[1], ah[2], ah[3], a_h_base + aoff);
            ldm_x4(al[0], al[1], al[2], al[3], a_l_base + aoff);
#pragma unroll
            for (int ni = 0; ni < 4; ni++) {
                mma_bf16(d[m][ni], ah, bh[ni]);
                mma_bf16(d[m][ni], ah, bl[ni]);
                mma_bf16(d[m][ni], al, bh[ni]);
            }
        }
    }

    // ---- epilogue ----
    const float* dmean = (const float*)(smc + SM_DM);
    float* yb = y + (size_t)n * CHW + p0;
    const int nlo = (lane & 3) * 2;
    const int mrow = lane >> 2;
#pragma unroll
    for (int m = 0; m < 2; m++) {
        const int ch0 = mg * 32 + m * 16 + mrow;
        const float dm0 = dmean[ch0];
        const float dm1 = dmean[ch0 + 8];
#pragma unroll
        for (int ni = 0; ni < 4; ni++) {
            const int col = wc0 + ni * 8 + nlo;
            float2 o0, o1;
            o0.x = d[m][ni][0] - dm0; o0.y = d[m][ni][1] - dm0;
            o1.x = d[m][ni][2] - dm1; o1.y = d[m][ni][3] - dm1;
            *(float2*)&yb[(size_t)ch0 * HW + col] = o0;
            *(float2*)&yb[(size_t)(ch0 + 8) * HW + col] = o1;
        }
    }
}

// =====================================================================
extern "C" void kernel_launch(void* const* d_in, const int* in_sizes, int n_in,
                              void* d_out, int out_size) {
    (void)in_sizes; (void)n_in; (void)out_size;
    const float* x = (const float*)d_in[0];
    float* y = (float*)d_out;

    cudaFuncSetAttribute(ns_kernel, cudaFuncAttributeMaxDynamicSharedMemorySize, NS_SMEM);
    cudaFuncSetAttribute(apply_mma_kernel, cudaFuncAttributeMaxDynamicSharedMemorySize, APPLY_SMEM);

    gram_kernel<<<GRID_GRAM, 256>>>(x);
    reduce_kernel<<<16, 256>>>();
    ns_kernel<<<1, 512, NS_SMEM>>>();
    apply_mma_kernel<<<GRID_APPLY, 256, APPLY_SMEM>>>(x, y);
}

// round 13
// speedup vs baseline: 1.0094x; 1.0094x over previous
#include <cuda_runtime.h>
#include <cstdint>

// Problem constants
#define Nn 32
#define Cc 64
#define HW 16384            // 128*128
#define CHW (Cc*HW)         // 1048576
#define NCOLS_S 58255
#define NCHUNK 911
#define EPSF 0.01f
#define GRID_GRAM 148
#define GRID_RED 16
#define GRID_APPLY 4096     // 524288 cols / 128 per block

typedef unsigned long long ull;
typedef unsigned int u32;

// bf16x2 pack: high 16 bits = bf16(a_hi), low 16 = bf16(b_lo)
__device__ __forceinline__ u32 bf2(float a_hi, float b_lo) {
    u32 r; asm("cvt.rn.bf16x2.f32 %0, %1, %2;" : "=r"(r) : "f"(a_hi), "f"(b_lo));
    return r;
}
__device__ __forceinline__ void ubf2(u32 v, float& lo, float& hi) {
    lo = __uint_as_float(v << 16);
    hi = __uint_as_float(v & 0xFFFF0000u);
}
__device__ __forceinline__ u32 smem_u32(const void* p) {
    u32 a;
    asm("{ .reg .u64 t; cvta.to.shared.u64 t, %1; cvt.u32.u64 %0, t; }" : "=r"(a) : "l"(p));
    return a;
}

// ---------------- mma.sync helpers ----------------
__device__ __forceinline__ void ldm_x4(u32& r0, u32& r1, u32& r2, u32& r3, u32 addr) {
    asm volatile("ldmatrix.sync.aligned.m8n8.x4.shared.b16 {%0,%1,%2,%3}, [%4];"
                 : "=r"(r0), "=r"(r1), "=r"(r2), "=r"(r3) : "r"(addr));
}
__device__ __forceinline__ void ldm_x4t(u32& r0, u32& r1, u32& r2, u32& r3, u32 addr) {
    asm volatile("ldmatrix.sync.aligned.m8n8.x4.trans.shared.b16 {%0,%1,%2,%3}, [%4];"
                 : "=r"(r0), "=r"(r1), "=r"(r2), "=r"(r3) : "r"(addr));
}
__device__ __forceinline__ void ldm_x2t(u32& r0, u32& r1, u32 addr) {
    asm volatile("ldmatrix.sync.aligned.m8n8.x2.trans.shared.b16 {%0,%1}, [%2];"
                 : "=r"(r0), "=r"(r1) : "r"(addr));
}
__device__ __forceinline__ void mma_bf16(float* d, const u32* a, const u32* b) {
    asm volatile(
        "mma.sync.aligned.m16n8k16.row.col.f32.bf16.bf16.f32 "
        "{%0,%1,%2,%3}, {%4,%5,%6,%7}, {%8,%9}, {%0,%1,%2,%3};"
        : "+f"(d[0]), "+f"(d[1]), "+f"(d[2]), "+f"(d[3])
        : "r"(a[0]), "r"(a[1]), "r"(a[2]), "r"(a[3]), "r"(b[0]), "r"(b[1]));
}

// ---------------- device scratch ----------------
__device__ float g_part[GRID_GRAM * 4096];
__device__ float g_rspart[GRID_GRAM * 64];
__device__ float g_gram[4096];
__device__ float g_rowsum[64];
__device__ __align__(16) u32 g_wpack[4096];   // [0:2048) Wh, [2048:4096) Wl
__device__ float g_dmean[64];
__device__ u32 g_red_done;                    // monotonic (graph-replay safe)

// =====================================================================
// Pass 1: Gram of subsampled columns + row sums (measured-best shape)
// =====================================================================
__global__ void __launch_bounds__(256) gram_kernel(const float* __restrict__ x) {
    __shared__ float asub[64][64];
    __shared__ float ps[256];

    const int t = threadIdx.x;
    const int bid = blockIdx.x;
    const int b = t & 63;
    const int g = t >> 6;
    const int i0 = (t >> 4) * 4, j0 = (t & 15) * 4;

    float acc[4][4];
#pragma unroll
    for (int p = 0; p < 4; p++)
#pragma unroll
        for (int q = 0; q < 4; q++) acc[p][q] = 0.f;
    float rs = 0.f;

    for (int chunk = bid; chunk < NCHUNK; chunk += GRID_GRAM) {
        float vals[16];
#pragma unroll
        for (int k = 0; k < 16; k++) {
            const int scol = g * 16 + k;
            const int s = chunk * 64 + scol;
            float v = 0.f;
            if (s < NCOLS_S) {
                const int col = s * 9;
                const int n = col >> 14;
                const int p = col & 16383;
                v = x[n * CHW + b * HW + p];
            }
            vals[k] = v;
            rs += v;
        }
        __syncthreads();
#pragma unroll
        for (int k = 0; k < 16; k++) asub[g * 16 + k][b] = vals[k];
        __syncthreads();

#pragma unroll 4
        for (int scol = 0; scol < 64; scol++) {
            const float4 av = *(const float4*)&asub[scol][i0];
            const float4 bv = *(const float4*)&asub[scol][j0];
            const float ar[4] = {av.x, av.y, av.z, av.w};
            const float br[4] = {bv.x, bv.y, bv.z, bv.w};
#pragma unroll
            for (int p = 0; p < 4; p++)
#pragma unroll
                for (int q = 0; q < 4; q++)
                    acc[p][q] = fmaf(ar[p], br[q], acc[p][q]);
        }
    }

    float* gp = &g_part[bid * 4096];
#pragma unroll
    for (int p = 0; p < 4; p++)
#pragma unroll
        for (int q = 0; q < 4; q++)
            gp[(i0 + p) * 64 + (j0 + q)] = acc[p][q];

    __syncthreads();
    ps[t] = rs;
    __syncthreads();
    if (t < 64)
        g_rspart[bid * 64 + t] = ps[t] + ps[t + 64] + ps[t + 128] + ps[t + 192];
}

// =====================================================================
// Fused reduce + Newton-Schulz. Grid 16, block 512.
// Every block reduces its 256-entry slice (2 k-slices of 74).
// The LAST block to finish (monotonic counter) runs NS inline.
// NS: dual-phase mma.sync schedule, 5 smem slots of bf16 hi/lo.
// =====================================================================
#define SLOT_BYTES 18432           // hi(9216) + lo(9216)
#define NS_SMEM (5 * SLOT_BYTES + 4096)

__device__ __forceinline__ void ns_mm64(char* smc, u32 sbase,
                                        int dst, int As, int Bs,
                                        int role, int lane, bool thalf) {
    const int mt = role & 3;
    const int nh = role >> 2;

    float d[4][4];
#pragma unroll
    for (int nt = 0; nt < 4; nt++)
#pragma unroll
        for (int r = 0; r < 4; r++) d[nt][r] = 0.f;

    const u32 Ahi = sbase + (u32)As * SLOT_BYTES;
    const u32 Alo = Ahi + 9216;
    const u32 Bhi = sbase + (u32)Bs * SLOT_BYTES;
    const u32 Blo = Bhi + 9216;

    const u32 a_base = (u32)(mt * 16 + (lane & 15)) * 144 + (u32)(lane >> 4) * 16;
    const u32 b_base = (u32)(lane & 15) * 144 + (u32)nh * 64;

#pragma unroll
    for (int ks = 0; ks < 4; ks++) {
        u32 ah[4], al[4];
        ldm_x4(ah[0], ah[1], ah[2], ah[3], Ahi + a_base + (u32)ks * 32);
        ldm_x4(al[0], al[1], al[2], al[3], Alo + a_base + (u32)ks * 32);
        const u32 brow = b_base + (u32)(ks * 16) * 144;
#pragma unroll
        for (int nt = 0; nt < 4; nt++) {
            u32 bh[2], bl[2];
            ldm_x2t(bh[0], bh[1], Bhi + brow + (u32)nt * 16);
            ldm_x2t(bl[0], bl[1], Blo + brow + (u32)nt * 16);
            mma_bf16(d[nt], ah, bh);
            mma_bf16(d[nt], ah, bl);
            mma_bf16(d[nt], al, bh);
        }
    }

    u32* Dhi = (u32*)(smc + dst * SLOT_BYTES);
    u32* Dlo = (u32*)(smc + dst * SLOT_BYTES + 9216);
    const int r0 = mt * 16 + (lane >> 2);
#pragma unroll
    for (int nt = 0; nt < 4; nt++) {
        const int c0 = nh * 32 + nt * 8 + (lane & 3) * 2;
        float v0 = d[nt][0], v1 = d[nt][1], v2 = d[nt][2], v3 = d[nt][3];
        if (thalf) {
            v0 = (r0 == c0     ? 1.5f : 0.f) - 0.5f * v0;
            v1 = (r0 == c0 + 1 ? 1.5f : 0.f) - 0.5f * v1;
            v2 = (r0 + 8 == c0     ? 1.5f : 0.f) - 0.5f * v2;
            v3 = (r0 + 8 == c0 + 1 ? 1.5f : 0.f) - 0.5f * v3;
        }
        {
            const u32 h = bf2(v1, v0);
            float e0, e1; ubf2(h, e0, e1);
            Dhi[r0 * 36 + (c0 >> 1)] = h;
            Dlo[r0 * 36 + (c0 >> 1)] = bf2(v1 - e1, v0 - e0);
        }
        {
            const u32 h = bf2(v3, v2);
            float e2, e3; ubf2(h, e2, e3);
            Dhi[(r0 + 8) * 36 + (c0 >> 1)] = h;
            Dlo[(r0 + 8) * 36 + (c0 >> 1)] = bf2(v3 - e3, v2 - e2);
        }
    }
}

__global__ void __launch_bounds__(512) reduce_ns_kernel() {
    extern __shared__ char smc[];
    const u32 sbase = smem_u32(smc);
    float* red = (float*)(smc + 5 * SLOT_BYTES);      // [512]
    volatile int* flag = (volatile int*)(smc + 5 * SLOT_BYTES + 2048);

    const int t = threadIdx.x;
    const int bid = blockIdx.x;
    const int wid = t >> 5;
    const int lane = t & 31;

    // ---- reduce slice: 256 idx per block, 2 k-slices ----
    {
        const int idx = bid * 256 + (t & 255);
        const int ks = t >> 8;
        float s = 0.f;
        for (int k = ks; k < GRID_GRAM; k += 2)
            s += g_part[k * 4096 + idx];
        red[t] = s;
        __syncthreads();
        if (t < 256)
            g_gram[bid * 256 + t] = red[t] + red[t + 256];
        if (bid == 0 && t >= 256 && t < 320) {
            const int j = t - 256;
            float r = 0.f;
            for (int k = 0; k < GRID_GRAM; k++) r += g_rspart[k * 64 + j];
            g_rowsum[j] = r;
        }
        __syncthreads();
    }

    // ---- last-block election (monotonic counter, no spinning) ----
    if (t == 0) {
        __threadfence();
        const u32 old = atomicAdd(&g_red_done, 1u);
        *flag = ((old % GRID_RED) == GRID_RED - 1) ? 1 : 0;
    }
    __syncthreads();
    if (!*flag) return;
    __threadfence();

    // ================= Newton-Schulz (last block only) =================
    const float invn = 1.0f / (float)NCOLS_S;
    const int prow = (t >> 2) & 63;
    const int pcol0 = (t & 3) * 16;
    float v[16];
    float ss = 0.f;
    if (t < 256) {
#pragma unroll
        for (int c = 0; c < 16; c++) {
            const int j = pcol0 + c;
            float val = g_gram[prow * 64 + j] * invn + ((prow == j) ? EPSF : 0.f);
            v[c] = val;
            ss += val * val;
        }
    }
    red[t] = (t < 256) ? ss : 0.f;
    __syncthreads();
    for (int off = 256; off > 0; off >>= 1) {
        if (t < off) red[t] += red[t + off];
        __syncthreads();
    }
    const float normA = sqrtf(red[0]);
    const float inv = 1.0f / normA;

    if (t < 256) {
        u32* Yhi = (u32*)(smc);
        u32* Ylo = (u32*)(smc + 9216);
        u32* Zhi = (u32*)(smc + SLOT_BYTES);
        u32* Zlo = (u32*)(smc + SLOT_BYTES + 9216);
#pragma unroll
        for (int p = 0; p < 8; p++) {
            const float y0 = v[2 * p] * inv;
            const float y1 = v[2 * p + 1] * inv;
            const u32 h = bf2(y1, y0);
            float e0, e1; ubf2(h, e0, e1);
            const int ui = prow * 36 + (pcol0 >> 1) + p;
            Yhi[ui] = h;
            Ylo[ui] = bf2(y1 - e1, y0 - e0);
            const int c0 = pcol0 + 2 * p;
            u32 ih = 0;
            if (prow == c0) ih = 0x00003F80u;
            else if (prow == c0 + 1) ih = 0x3F800000u;
            Zhi[ui] = ih;
            Zlo[ui] = 0u;
        }
    }
    __syncthreads();

    int Y = 0, Z = 1, T = 2, U1 = 3, U2 = 4;
    for (int it = 0; it < 5; it++) {
        if (wid < 8)
            ns_mm64(smc, sbase, T, Z, Y, wid, lane, true);
        __syncthreads();
        if (it < 4) {
            if (wid < 8)
                ns_mm64(smc, sbase, U1, Y, T, wid, lane, false);
            else
                ns_mm64(smc, sbase, U2, T, Z, wid - 8, lane, false);
            __syncthreads();
            const int oldY = Y, oldZ = Z;
            Y = U1; Z = U2; U1 = oldY; U2 = oldZ;
        } else {
            if (wid < 8)
                ns_mm64(smc, sbase, U1, T, Z, wid, lane, false);
            __syncthreads();
            Z = U1;
        }
    }

    const float sc = 1.0f / sqrtf(normA);
    const u32* Zhi = (const u32*)(smc + Z * SLOT_BYTES);
    const u32* Zlo = (const u32*)(smc + Z * SLOT_BYTES + 9216);

    if (t < 256) {
#pragma unroll
        for (int p = 0; p < 8; p++) {
            const int ui = prow * 36 + (pcol0 >> 1) + p;
            float h0, h1, l0, l1;
            ubf2(Zhi[ui], h0, h1);
            ubf2(Zlo[ui], l0, l1);
            const float d0 = (h0 + l0) * sc;
            const float d1 = (h1 + l1) * sc;
            const u32 h = bf2(d1, d0);
            float e0, e1; ubf2(h, e0, e1);
            const u32 gi = prow * 32 + (pcol0 >> 1) + p;
            g_wpack[gi] = h;
            g_wpack[2048 + gi] = bf2(d1 - e1, d0 - e0);
        }
    }
    __syncthreads();
    if (t < 64) {
        float dm = 0.f;
        for (int p = 0; p < 32; p++) {
            float h0, h1, l0, l1;
            ubf2(Zhi[t * 36 + p], h0, h1);
            ubf2(Zlo[t * 36 + p], l0, l1);
            dm += (h0 + l0) * sc * (g_rowsum[2 * p] * invn);
            dm += (h1 + l1) * sc * (g_rowsum[2 * p + 1] * invn);
        }
        g_dmean[t] = dm;
    }
}

// =====================================================================
// Pass 2 (mma.sync bf16 split-precision), 128-col tiles.
// Warp w: m-group = w>>2 (2 m-tiles), col-strip = (w&3)*32 (4 n-tiles).
// B via ldmatrix.x4.trans (2 n-tile fragments per instr).
// Epilogue: stage to dead X smem (padded), stream 512B-coalesced stores.
// =====================================================================
#define XSTRIDE_H 136              // bf16 per X row (272B)
#define YSTRIDE 136                // f32 per staged output row (544B)
#define SM_XH 0
#define SM_XL 17408
#define SM_WH 34816
#define SM_WL 44032
#define SM_DM 53248
#define APPLY_SMEM (SM_DM + 256)

__global__ void __launch_bounds__(256, 3) apply_mma_kernel(const float* __restrict__ x,
                                                           float* __restrict__ y) {
    extern __shared__ char smc[];
    const u32 sbase = smem_u32(smc);
    const int t = threadIdx.x;
    const int wid = t >> 5;
    const int lane = t & 31;

    // ---- stage W (padded rows: 36 u32 = 72 bf16) + dmean ----
    {
        u32* wh = (u32*)(smc + SM_WH);
        u32* wl = (u32*)(smc + SM_WL);
#pragma unroll
        for (int k = 0; k < 8; k++) {
            const int u = k * 256 + t;
            const int i = u >> 5;
            const int jc = u & 31;
            wh[i * 36 + jc] = g_wpack[u];
            wl[i * 36 + jc] = g_wpack[2048 + u];
        }
        if (t < 64) ((float*)(smc + SM_DM))[t] = g_dmean[t];
    }

    // ---- stage X tile (64 rows x 128 cols): f32 -> bf16 hi/lo ----
    const int gcol0 = blockIdx.x * 128;
    const int n = gcol0 >> 14;
    const int p0 = gcol0 & 16383;
    const float* xb = x + (size_t)n * CHW + p0;

    {
        const int c = lane * 4;
        const int row0 = wid * 8;
        ull* xhp = (ull*)(smc + SM_XH);
        ull* xlp = (ull*)(smc + SM_XL);
#pragma unroll
        for (int r = 0; r < 8; r++) {
            const int row = row0 + r;
            const float4 vv = *(const float4*)&xb[(size_t)row * HW + c];
            const u32 h0 = bf2(vv.y, vv.x);
            const u32 h1 = bf2(vv.w, vv.z);
            float e0, e1, e2, e3;
            ubf2(h0, e0, e1);
            ubf2(h1, e2, e3);
            const u32 l0 = bf2(vv.y - e1, vv.x - e0);
            const u32 l1 = bf2(vv.w - e3, vv.z - e2);
            const int di = (row * XSTRIDE_H + c) >> 2;
            xhp[di] = ((ull)h1 << 32) | h0;
            xlp[di] = ((ull)l1 << 32) | l0;
        }
    }
    __syncthreads();

    // ---- MMA mainloop: warp = 2 m-tiles x 4 n-tiles ----
    const int cs = wid & 3;
    const int mg = wid >> 2;
    const int wc0 = cs * 32;

    float d[2][4][4];
#pragma unroll
    for (int m = 0; m < 2; m++)
#pragma unroll
        for (int ni = 0; ni < 4; ni++)
#pragma unroll
            for (int r = 0; r < 4; r++) d[m][ni][r] = 0.f;

    const u32 a_h_base = sbase + SM_WH + (u32)(mg * 32 + (lane & 15)) * 144 + (u32)(lane >> 4) * 16;
    const u32 a_l_base = a_h_base + (SM_WL - SM_WH);
    // x4.trans lane addressing: matrix m4 = lane>>3
    //   krow = (m4&1)*8 + (lane&7), colblk = (m4>>1)*8
    const int m4 = lane >> 3;
    const u32 b4_off = (u32)((m4 & 1) * 8 + (lane & 7)) * 272
                     + (u32)(wc0 + (m4 >> 1) * 8) * 2;
    const u32 b4_h_base = sbase + SM_XH + b4_off;
    const u32 b4_l_base = b4_h_base + (SM_XL - SM_XH);

#pragma unroll
    for (int ks = 0; ks < 4; ks++) {
        u32 bh[4][2], bl[4][2];
        const u32 brow = (u32)(ks * 16) * 272;
#pragma unroll
        for (int nib = 0; nib < 2; nib++) {
            // one x4.trans covers n-tiles 2*nib and 2*nib+1 (16 cols)
            ldm_x4t(bh[2 * nib][0], bh[2 * nib][1], bh[2 * nib + 1][0], bh[2 * nib + 1][1],
                    b4_h_base + brow + (u32)nib * 32);
            ldm_x4t(bl[2 * nib][0], bl[2 * nib][1], bl[2 * nib + 1][0], bl[2 * nib + 1][1],
                    b4_l_base + brow + (u32)nib * 32);
        }
#pragma unroll
        for (int m = 0; m < 2; m++) {
            u32 ah[4], al[4];
            const u32 aoff = (u32)(m * 16) * 144 + (u32)ks * 32;
            ldm_x4(ah[0], ah[1], ah[2], ah[3], a_h_base + aoff);
            ldm_x4(al[0], al[1], al[2], al[3], a_l_base + aoff);
#pragma unroll
            for (int ni = 0; ni < 4; ni++) {
                mma_bf16(d[m][ni], ah, bh[ni]);
                mma_bf16(d[m][ni], ah, bl[ni]);
                mma_bf16(d[m][ni], al, bh[ni]);
            }
        }
    }

    // ---- epilogue: stage to smem (X regions dead), then coalesced out ----
    const float* dmean = (const float*)(smc + SM_DM);
    const int nlo = (lane & 3) * 2;
    const int mrow = lane >> 2;

    __syncthreads();   // all warps done reading X smem
    float* yst = (float*)(smc + SM_XH);   // [64][YSTRIDE] floats (34816B)
#pragma unroll
    for (int m = 0; m < 2; m++) {
        const int ch0 = mg * 32 + m * 16 + mrow;
        const float dm0 = dmean[ch0];
        const float dm1 = dmean[ch0 + 8];
#pragma unroll
        for (int ni = 0; ni < 4; ni++) {
            const int col = wc0 + ni * 8 + nlo;
            yst[ch0 * YSTRIDE + col]           = d[m][ni][0] - dm0;
            yst[ch0 * YSTRIDE + col + 1]       = d[m][ni][1] - dm0;
            yst[(ch0 + 8) * YSTRIDE + col]     = d[m][ni][2] - dm1;
            yst[(ch0 + 8) * YSTRIDE + col + 1] = d[m][ni][3] - dm1;
        }
    }
    __syncthreads();

    float* yb = y + (size_t)n * CHW + p0;
#pragma unroll
    for (int r = 0; r < 8; r++) {
        const int row = r * 8 + wid;
        const float4 v = *(const float4*)&yst[row * YSTRIDE + lane * 4];
        *(float4*)&yb[(size_t)row * HW + lane * 4] = v;
    }
}

// =====================================================================
extern "C" void kernel_launch(void* const* d_in, const int* in_sizes, int n_in,
                              void* d_out, int out_size) {
    (void)in_sizes; (void)n_in; (void)out_size;
    const float* x = (const float*)d_in[0];
    float* y = (float*)d_out;

    cudaFuncSetAttribute(reduce_ns_kernel, cudaFuncAttributeMaxDynamicSharedMemorySize, NS_SMEM);
    cudaFuncSetAttribute(apply_mma_kernel, cudaFuncAttributeMaxDynamicSharedMemorySize, APPLY_SMEM);

    gram_kernel<<<GRID_GRAM, 256>>>(x);
    reduce_ns_kernel<<<GRID_RED, 512, NS_SMEM>>>();
    apply_mma_kernel<<<GRID_APPLY, 256, APPLY_SMEM>>>(x, y);
}